// round 7
// baseline (speedup 1.0000x reference)
#include <cuda_runtime.h>
#include <cuda_bf16.h>

#define NBINS 100
#define NROWS 102          // guard rows: j in [0,100] -> rows j and j+1
#define EPSF  1e-10f
#define COLS  16           // lane pair (l, l+16) shares column l&15, split by row parity
#define GRID_BLOCKS 2432   // 152 SMs * 16 blocks
#define DEPTH 6            // float4-pairs in flight per thread (12 LDG.128)

__device__ float        g_hist[NBINS];
__device__ float        g_wss[NBINS];
__device__ unsigned int g_count;

typedef unsigned long long u64;

__device__ __forceinline__ u64 pack2(float lo, float hi) {
    u64 r; asm("mov.b64 %0, {%1, %2};" : "=l"(r) : "f"(lo), "f"(hi)); return r;
}
__device__ __forceinline__ u64 addf32x2(u64 a, u64 b) {
    u64 r; asm("add.rn.f32x2 %0, %1, %2;" : "=l"(r) : "l"(a), "l"(b)); return r;
}

// One element: compute both contributions, swap the other-parity item with the
// partner lane (xor 16), then 2 race-free RMWs into this lane's parity rows.
__device__ __forceinline__ void process_elem(u64* __restrict__ shl,
                                             float of, float wf,
                                             float invd, float nb0, bool isB)
{
    float t  = fmaf(of, invd, nb0);
    float jf = floorf(t);
    float fr = t - jf;
    int   j  = (int)jf;
    j = min(max(j, 0), NROWS - 2);          // 0..100
    float frw = fr * wf;
    float wp  = wf - frw;                    // (1-fr)*wf
    u64 P = pack2(wp,  wp * wp);             // -> row j
    u64 S = pack2(frw, frw * frw);           // -> row j+1

    bool jodd = (j & 1) != 0;
    int er = jodd ? j + 1 : j;               // even row
    int orr = jodd ? j : j + 1;              // odd row
    u64 ev = jodd ? S : P;
    u64 ov = jodd ? P : S;

    // group A (lanes 0-15) keeps even, sends odd; group B keeps odd, sends even
    int sr = isB ? er : orr;
    u64 sv = isB ? ev : ov;
    int kr = isB ? orr : er;
    u64 kv = isB ? ov : ev;

    int rr = __shfl_xor_sync(0xFFFFFFFFu, sr, 16);
    u64 rv = __shfl_xor_sync(0xFFFFFFFFu, sv, 16);

    u64* p0 = shl + kr * COLS;
    u64* p1 = shl + rr * COLS;
    u64 l0 = p0[0];
    u64 l1 = p1[0];
    bool eq = (kr == rr);
    u64 s0 = addf32x2(l0, kv);
    u64 s1 = addf32x2(l1, eq ? addf32x2(rv, kv) : rv);
    p0[0] = s0;
    p1[0] = s1;        // stored last: on eq the merged value wins
}

__device__ __forceinline__ void process4(u64* __restrict__ shl,
                                         float4 o, float4 w,
                                         float invd, float nb0, bool isB)
{
    process_elem(shl, o.x, w.x, invd, nb0, isB);
    process_elem(shl, o.y, w.y, invd, nb0, isB);
    process_elem(shl, o.z, w.z, invd, nb0, isB);
    process_elem(shl, o.w, w.w, invd, nb0, isB);
}

__global__ __launch_bounds__(32, 16) void fused_k(
    const float4* __restrict__ obs4,
    const float4* __restrict__ wts4,
    const float*  __restrict__ obs_s,
    const float*  __restrict__ wts_s,
    const float*  __restrict__ bins,
    const float*  __restrict__ histo_exp,
    float*        __restrict__ out,
    int nvec, int n)
{
    __shared__ u64 sh[NROWS * COLS];   // cell = packed (hist, wss)
    const int lane = threadIdx.x;
    const bool isB = lane >= 16;

    #pragma unroll
    for (int i = lane; i < NROWS * COLS; i += 32)
        sh[i] = 0ULL;
    __syncwarp();

    const float b0   = __ldg(&bins[0]);
    const float bN   = __ldg(&bins[NBINS]);
    const float invd = (float)NBINS / (bN - b0);
    const float nb0  = -b0 * invd;

    u64* shl = &sh[lane & 15];
    const int stride = GRID_BLOCKS * 32;
    const int bbase  = blockIdx.x * 32;

    // Warp-uniform trip count (shuffles in the loop body require full warp).
    int remain = nvec - bbase;                       // same for all lanes
    int niter  = (remain > 0) ? (remain + DEPTH * stride - 1) / (DEPTH * stride) : 0;

    // Rotating prefetch pipeline; inactive slots: clamped index, zeroed weight.
    float4 O[DEPTH], W[DEPTH];
    #pragma unroll
    for (int d = 0; d < DEPTH; d++) {
        int vi   = bbase + lane + d * stride;
        bool act = vi < nvec;
        int idx  = act ? vi : (nvec > 0 ? nvec - 1 : 0);
        O[d] = obs4[idx];
        float4 ww = wts4[idx];
        if (!act) ww = make_float4(0.0f, 0.0f, 0.0f, 0.0f);
        W[d] = ww;
    }

    for (int k = 0; k < niter; k++) {
        #pragma unroll
        for (int d = 0; d < DEPTH; d++) {
            int vi   = bbase + lane + ((k + 1) * DEPTH + d) * stride;
            bool act = vi < nvec;
            int idx  = act ? vi : (nvec - 1);
            float4 no = obs4[idx];
            float4 nw = wts4[idx];
            process4(shl, O[d], W[d], invd, nb0, isB);
            O[d] = no;
            W[d] = act ? nw : make_float4(0.0f, 0.0f, 0.0f, 0.0f);
        }
    }

    // Scalar tail (N % 4), block 0 only; single uniform masked pass.
    if (blockIdx.x == 0 && (nvec * 4) < n) {
        int i    = nvec * 4 + lane;
        bool act = i < n;
        int idx  = act ? i : (n - 1);
        float of = obs_s[idx];
        float wf = act ? wts_s[idx] : 0.0f;
        process_elem(shl, of, wf, invd, nb0, isB);
    }
    __syncwarp();

    // Rotated per-row reduction over 16 cols; rows [1,98] map to bins.
    const float2* shf = (const float2*)sh;
    #pragma unroll
    for (int g = 0; g < 4; g++) {
        int r = g * 32 + lane;
        if (r < NROWS) {
            float h = 0.0f, s = 0.0f;
            #pragma unroll
            for (int t = 0; t < 16; t++) {
                int c = (lane + t) & 15;
                float2 vv = shf[r * COLS + c];
                h += vv.x; s += vv.y;
            }
            if (r >= 1 && r <= NBINS - 2) {
                atomicAdd(&g_hist[r], h);
                atomicAdd(&g_wss[r], s);
            }
        }
    }

    // Last-block-done: final chi^2 + reset for next graph replay.
    __syncwarp();
    __threadfence();
    unsigned int done = 0;
    if (lane == 0) done = atomicAdd(&g_count, 1u);
    done = __shfl_sync(0xFFFFFFFFu, done, 0);
    if (done == (unsigned)(GRID_BLOCKS - 1)) {
        __threadfence();
        float hs[4], ss[4], he[4];
        float hsum = 0.0f, esum = 0.0f;
        #pragma unroll
        for (int g = 0; g < 4; g++) {
            int b = g * 32 + lane;
            bool ok = (b < NBINS);
            hs[g] = ok ? __ldcg(&g_hist[b]) : 0.0f;
            ss[g] = ok ? __ldcg(&g_wss[b])  : 0.0f;
            he[g] = ok ? __ldg(&histo_exp[b]) : 0.0f;
            hsum += hs[g];
            esum += he[g];
        }
        #pragma unroll
        for (int o = 16; o > 0; o >>= 1) {
            hsum += __shfl_xor_sync(0xFFFFFFFFu, hsum, o);
            esum += __shfl_xor_sync(0xFFFFFFFFu, esum, o);
        }
        const float inv_ss2 = 1.0f / ((hsum + EPSF) * (hsum + EPSF));
        const float inv_se2 = 1.0f / ((esum + EPSF) * (esum + EPSF));
        const float inv_ss  = 1.0f / hsum;
        const float inv_se  = 1.0f / esum;
        float chi = 0.0f;
        #pragma unroll
        for (int g = 0; g < 4; g++) {
            int b = g * 32 + lane;
            if (b < NBINS) {
                float unc_sim = ss[g] * inv_ss2 + EPSF;
                float unc_exp = he[g] * (1.0f - he[g] * inv_se) * inv_se2 + EPSF;
                float d = hs[g] * inv_ss - he[g] * inv_se;
                chi += d * d / (unc_sim + unc_exp);
            }
        }
        #pragma unroll
        for (int o = 16; o > 0; o >>= 1)
            chi += __shfl_xor_sync(0xFFFFFFFFu, chi, o);
        if (lane == 0) out[0] = chi;

        #pragma unroll
        for (int g = 0; g < 4; g++) {
            int b = g * 32 + lane;
            if (b < NBINS) {
                __stcg(&g_hist[b], 0.0f);
                __stcg(&g_wss[b], 0.0f);
            }
        }
        __threadfence();
        if (lane == 0) atomicExch(&g_count, 0u);
    }
}

extern "C" void kernel_launch(void* const* d_in, const int* in_sizes, int n_in,
                              void* d_out, int out_size) {
    const float* sim  = (const float*)d_in[0];
    // d_in[1] = exp_observable: unused in the fixed_binning branch
    const float* wts  = (const float*)d_in[2];
    const float* bins = (const float*)d_in[3];
    const float* he   = (const float*)d_in[4];
    int n    = in_sizes[0];
    int nvec = n / 4;

    cudaFuncSetAttribute(fused_k, cudaFuncAttributePreferredSharedMemoryCarveout, 100);

    fused_k<<<GRID_BLOCKS, 32>>>((const float4*)sim, (const float4*)wts,
                                 sim, wts, bins, he, (float*)d_out, nvec, n);
}